// round 13
// baseline (speedup 1.0000x reference)
#include <cuda_runtime.h>
#include <cuda_fp16.h>
#include <cstdint>

// ---------------------------------------------------------------------------
// TimeAwareKAN via single GEMM  out[m,o] = sum_k F[m,k] * W[o,k] + b[o]
//   M = 49152, K = 768 (6 families x 128), O = 512
// R12: R11 shell (2 CTAs/SM, 3-stage cp.async, BM=BN=128, 4 warps, 64x64
// warp tiles) + register double-buffering of ldmatrix fragments across
// k-steps: frags(s+1) load while mma(s) executes -> smem latency hidden.
// t_indices is int32 on device (JAX x64 disabled).
// ---------------------------------------------------------------------------

#define B_   4
#define H_   24
#define N_   512
#define C_   120
#define D_   128
#define O_   512
#define G_   5
#define M_TOTAL (B_ * H_ * N_)
#define K_TOTAL 768

#define BM 128
#define BN 128
#define KC 64                    // 64 fp16 = 128B rows -> SW128 native
#define NCHUNK (K_TOTAL / KC)    // 12
#define THREADS 128
#define NSTAGE 3

#define STAGE_BYTES 32768
#define SMEM_BYTES  (NSTAGE * STAGE_BYTES)   // 96KB -> 2 CTAs/SM

__device__ __half g_W_h[O_ * K_TOTAL];            // 0.75 MB
__device__ __half g_F[(size_t)M_TOTAL * K_TOTAL]; // 75.5 MB scratch

__global__ void prep_W(const float* __restrict__ base_w,
                       const float* __restrict__ spline_w) {
    int idx = blockIdx.x * blockDim.x + threadIdx.x;
    if (idx >= O_ * K_TOTAL) return;
    int n = idx / K_TOTAL, k = idx - n * K_TOTAL;
    int j = k >> 7, i = k & 127;
    float w = (j == 0) ? base_w[n * D_ + i]
                       : spline_w[(n * D_ + i) * G_ + (j - 1)];
    g_W_h[idx] = __float2half(w);
}

// ---- Feature kernel: one thread -> 8 contiguous k of one row ----
__global__ __launch_bounds__(512)
void feat_kernel(const float* __restrict__ x,
                 const int* __restrict__ t_indices,
                 const float* __restrict__ time_emb) {
    int g = blockIdx.x * 512 + threadIdx.x;        // < M*96
    int m = g / 96, c8 = g - m * 96;
    int j = c8 >> 4, i0 = (c8 & 15) * 8;

    float4 a, b;
    if (i0 < C_) {
        a = *(const float4*)(x + (size_t)m * C_ + i0);
        b = *(const float4*)(x + (size_t)m * C_ + i0 + 4);
    } else {                                       // i0 == 120: time emb
        int h = (m >> 9) % H_;
        int ts = t_indices[h];
        ts = min(max(ts, 0), H_ - 1);
        a = *(const float4*)(time_emb + ts * 8);
        b = *(const float4*)(time_emb + ts * 8 + 4);
    }
    float v[8] = {a.x, a.y, a.z, a.w, b.x, b.y, b.z, b.w};
    float f[8];
    if (j == 0) {
#pragma unroll
        for (int e = 0; e < 8; ++e)
            f[e] = __fdividef(v[e], 1.0f + __expf(-v[e]));
    } else {
        const float gc = -1.0f + 0.5f * (float)(j - 1);
#pragma unroll
        for (int e = 0; e < 8; ++e) {
            float t = (v[e] - gc) * 2.0f;
            f[e] = __expf(-t * t);
        }
    }
    __half2 h0 = __floats2half2_rn(f[0], f[1]);
    __half2 h1 = __floats2half2_rn(f[2], f[3]);
    __half2 h2 = __floats2half2_rn(f[4], f[5]);
    __half2 h3 = __floats2half2_rn(f[6], f[7]);
    uint4 o;
    o.x = *(uint32_t*)&h0; o.y = *(uint32_t*)&h1;
    o.z = *(uint32_t*)&h2; o.w = *(uint32_t*)&h3;
    *(uint4*)(g_F + (size_t)m * K_TOTAL + j * 128 + i0) = o;
}

// ---------------- helpers ----------------
__device__ __forceinline__ uint32_t s2u(const void* p) {
    uint32_t a;
    asm("{ .reg .u64 t; cvta.to.shared.u64 t, %1; cvt.u32.u64 %0, t; }"
        : "=r"(a) : "l"(p));
    return a;
}
#define SWZ(o) ((o) ^ (((o) >> 3) & 0x70))

__device__ __forceinline__ void ldsm4(uint32_t* r, uint32_t addr) {
    asm volatile("ldmatrix.sync.aligned.m8n8.x4.shared.b16 {%0,%1,%2,%3}, [%4];"
        : "=r"(r[0]), "=r"(r[1]), "=r"(r[2]), "=r"(r[3]) : "r"(addr));
}
__device__ __forceinline__ void mma16816(float* c, const uint32_t* a,
                                         const uint32_t* b) {
    asm volatile(
        "mma.sync.aligned.m16n8k16.row.col.f32.f16.f16.f32 "
        "{%0,%1,%2,%3}, {%4,%5,%6,%7}, {%8,%9}, {%0,%1,%2,%3};"
        : "+f"(c[0]), "+f"(c[1]), "+f"(c[2]), "+f"(c[3])
        : "r"(a[0]), "r"(a[1]), "r"(a[2]), "r"(a[3]), "r"(b[0]), "r"(b[1]));
}

__global__ __launch_bounds__(THREADS, 2)
void kan_hmma_kernel(const float* __restrict__ base_b,
                     float* __restrict__ out) {
    extern __shared__ char smem[];
    const uint32_t sb = s2u(smem);
    const int tid = threadIdx.x, wid = tid >> 5, lane = tid & 31;
    const int m0 = blockIdx.y * BM, o0 = blockIdx.x * BN;

    const int warp_m = wid & 1;        // 2 x 64-row tiles
    const int warp_n = wid >> 1;       // 2 x 64-col tiles

    // ---- per-lane ldmatrix address components (SW128) ----
    const uint32_t kaoff = ((lane >> 4) & 1) * 16;
    uint32_t aB[4], aX[4];
#pragma unroll
    for (int t = 0; t < 4; ++t) {
        int r = warp_m * 64 + t * 16 + ((lane >> 3) & 1) * 8 + (lane & 7);
        aB[t] = r * 128;
        aX[t] = (r & 7) * 16;
    }
    const uint32_t kboff = ((lane >> 3) & 1) * 16;
    uint32_t bB[4], bX[4];
#pragma unroll
    for (int ng = 0; ng < 4; ++ng) {
        int r = warp_n * 64 + ng * 16 + ((lane >> 4) & 1) * 8 + (lane & 7);
        bB[ng] = r * 128;
        bX[ng] = (r & 7) * 16;
    }

    float acc[4][8][4];                 // [m16 tile][n8 tile][frag] = 128 regs
#pragma unroll
    for (int t = 0; t < 4; ++t)
#pragma unroll
        for (int j = 0; j < 8; ++j)
#pragma unroll
            for (int e = 0; e < 4; ++e) acc[t][j][e] = 0.0f;

    auto issue_chunk = [&](int kt) {
        const int stage = kt % NSTAGE;
        const int k0 = kt * KC;
        const uint32_t fbase = sb + stage * STAGE_BYTES;
        const uint32_t wbase = fbase + 16384;
        // F: 128 rows x 8 units = 1024 -> 8/thread
#pragma unroll
        for (int s = 0; s < 8; ++s) {
            int v = tid + THREADS * s;
            int r = v >> 3, u = v & 7;
            const __half* src = g_F + (size_t)(m0 + r) * K_TOTAL + k0 + u * 8;
            uint32_t dst = fbase + SWZ((uint32_t)(r * 128 + u * 16));
            asm volatile("cp.async.cg.shared.global [%0], [%1], 16;"
                         :: "r"(dst), "l"(src));
        }
        // W: 128 rows x 8 units = 1024 -> 8/thread
#pragma unroll
        for (int s = 0; s < 8; ++s) {
            int v = tid + THREADS * s;
            int r = v >> 3, u = v & 7;
            const __half* src = g_W_h + (size_t)(o0 + r) * K_TOTAL + k0 + u * 8;
            uint32_t dst = wbase + SWZ((uint32_t)(r * 128 + u * 16));
            asm volatile("cp.async.cg.shared.global [%0], [%1], 16;"
                         :: "r"(dst), "l"(src));
        }
        asm volatile("cp.async.commit_group;" ::: "memory");
    };

    // ---- prologue: fill 2 stages ----
    issue_chunk(0);
    issue_chunk(1);
    asm volatile("cp.async.wait_group 1;" ::: "memory");   // chunk 0 resident
    __syncthreads();

    // fragment double buffers
    uint32_t ahb[2][4][4], bhb[2][4][4];

    // ---- main loop: one commit group per iteration ----
#pragma unroll 1
    for (int kt = 0; kt < NCHUNK; ++kt) {
        const uint32_t fb = sb + (kt % NSTAGE) * STAGE_BYTES;
        const uint32_t wb = fb + 16384;

        // load s=0 fragments first, then hide cp.async issue in ldsm latency
        {
            const uint32_t ka = kaoff;
            const uint32_t kb = kboff;
#pragma unroll
            for (int t = 0; t < 4; ++t)
                ldsm4(ahb[0][t], fb + aB[t] + (ka ^ aX[t]));
#pragma unroll
            for (int ng = 0; ng < 4; ++ng)
                ldsm4(bhb[0][ng], wb + bB[ng] + (kb ^ bX[ng]));
        }

        // stage (kt+2)%3 != kt%3 and != (kt+1)%3 reads: safe
        if (kt + 2 < NCHUNK) {
            issue_chunk(kt + 2);
        } else {
            asm volatile("cp.async.commit_group;" ::: "memory");  // empty group
        }

#pragma unroll
        for (int s = 0; s < 4; ++s) {
            const int pb = s & 1;
            if (s < 3) {
                const uint32_t ka = (s + 1) * 32 + kaoff;
                const uint32_t kb = (s + 1) * 32 + kboff;
#pragma unroll
                for (int t = 0; t < 4; ++t)
                    ldsm4(ahb[pb ^ 1][t], fb + aB[t] + (ka ^ aX[t]));
#pragma unroll
                for (int ng = 0; ng < 4; ++ng)
                    ldsm4(bhb[pb ^ 1][ng], wb + bB[ng] + (kb ^ bX[ng]));
            }
#pragma unroll
            for (int ng = 0; ng < 4; ++ng) {
#pragma unroll
                for (int t = 0; t < 4; ++t) {
                    mma16816(acc[t][ng * 2 + 0], ahb[pb][t], bhb[pb][ng] + 0);
                    mma16816(acc[t][ng * 2 + 1], ahb[pb][t], bhb[pb][ng] + 2);
                }
            }
        }

        // pending groups: kt+1, kt+2 -> keep <=1 so chunk kt+1 is resident
        asm volatile("cp.async.wait_group 1;" ::: "memory");
        __syncthreads();
    }

    // ---- epilogue: + bias, float2 stores ----
    {
        const float* bb = base_b + o0 + warp_n * 64;
        float2 bi[8];
#pragma unroll
        for (int j = 0; j < 8; ++j)
            bi[j] = *(const float2*)(bb + j * 8 + (lane & 3) * 2);
#pragma unroll
        for (int t = 0; t < 4; ++t) {
            int r0 = m0 + warp_m * 64 + t * 16 + (lane >> 2);
            float* p0 = out + (size_t)r0 * O_ + o0 + warp_n * 64;
            float* p1 = p0 + (size_t)8 * O_;
#pragma unroll
            for (int j = 0; j < 8; ++j) {
                int col = j * 8 + (lane & 3) * 2;
                float2 v0, v1;
                v0.x = acc[t][j][0] + bi[j].x;
                v0.y = acc[t][j][1] + bi[j].y;
                v1.x = acc[t][j][2] + bi[j].x;
                v1.y = acc[t][j][3] + bi[j].y;
                *(float2*)(p0 + col) = v0;
                *(float2*)(p1 + col) = v1;
            }
        }
    }
}

extern "C" void kernel_launch(void* const* d_in, const int* in_sizes, int n_in,
                              void* d_out, int out_size) {
    const float* x         = (const float*)d_in[0];
    const int*   t_indices = (const int*)d_in[1];   // int32 (JAX x64 disabled)
    const float* time_emb  = (const float*)d_in[2];
    const float* base_w    = (const float*)d_in[3];
    const float* base_b    = (const float*)d_in[4];
    const float* spline_w  = (const float*)d_in[5];
    float* out = (float*)d_out;

    {
        int total = O_ * K_TOTAL;
        prep_W<<<(total + 255) / 256, 256>>>(base_w, spline_w);
    }
    // Materialize F once: M*96 8-wide groups, 512 thr/blk
    feat_kernel<<<(M_TOTAL * 96) / 512, 512>>>(x, t_indices, time_emb);

    cudaFuncSetAttribute(kan_hmma_kernel,
                         cudaFuncAttributeMaxDynamicSharedMemorySize, SMEM_BYTES);
    dim3 grid(O_ / BN, M_TOTAL / BM);   // (4, 384) = 1536 CTAs, 2/SM
    kan_hmma_kernel<<<grid, THREADS, SMEM_BYTES>>>(base_b, out);
}